// round 3
// baseline (speedup 1.0000x reference)
#include <cuda_runtime.h>
#include <math.h>

#define PI_F 3.14159265358979323846f
#define MARGIN_F 9.0f

#define DIM 512
#define HALF 256
#define NUM_REL 64
#define NB 1024                // head buckets for counting sort
#define MAX_EDGES 1048576

// Precomputed rotation tables: 64 relations x 256 dims of cos/sin (128 KB).
__device__ float g_cosT[NUM_REL * HALF];
__device__ float g_sinT[NUM_REL * HALF];

// Counting-sort scratch
__device__ int  g_count[NB];
__device__ int  g_offset[NB];
__device__ int4 g_perm[MAX_EDGES];   // (head, tail, rel, orig_idx)

__global__ void precompute_rot_kernel(const float* __restrict__ relation_emb) {
    int i = blockIdx.x * blockDim.x + threadIdx.x;
    if (i < NUM_REL * HALF) {
        float phase = relation_emb[i] * (PI_F / MARGIN_F);
        float s, c;
        sincosf(phase, &s, &c);
        g_cosT[i] = c;
        g_sinT[i] = s;
    }
}

__global__ void zero_count_kernel() {
    int i = blockIdx.x * blockDim.x + threadIdx.x;
    if (i < NB) g_count[i] = 0;
}

__device__ __forceinline__ int bucket_of(int h, int num_nodes) {
    return (int)(((unsigned long long)(unsigned)h * NB) / (unsigned)num_nodes);
}

__global__ void hist_kernel(const int* __restrict__ edge_index,
                            int num_edges, int num_nodes) {
    int e = blockIdx.x * blockDim.x + threadIdx.x;
    if (e < num_edges) {
        int b = bucket_of(edge_index[e], num_nodes);
        atomicAdd(&g_count[b], 1);
    }
}

// Single-block exclusive scan over NB counters (Hillis-Steele in smem).
__global__ void scan_kernel() {
    __shared__ int tmp[NB];
    int t = threadIdx.x;
    tmp[t] = g_count[t];
    __syncthreads();
    #pragma unroll
    for (int off = 1; off < NB; off <<= 1) {
        int v = (t >= off) ? tmp[t - off] : 0;
        __syncthreads();
        tmp[t] += v;
        __syncthreads();
    }
    g_offset[t] = (t == 0) ? 0 : tmp[t - 1];
}

__global__ void scatter_kernel(const int* __restrict__ edge_index,
                               const int* __restrict__ rel_type,
                               int num_edges, int num_nodes) {
    int e = blockIdx.x * blockDim.x + threadIdx.x;
    if (e < num_edges) {
        int h = edge_index[e];
        int t = edge_index[num_edges + e];
        int b = bucket_of(h, num_nodes);
        int p = atomicAdd(&g_offset[b], 1);
        g_perm[p] = make_int4(h, t, rel_type[e], e);
    }
}

__device__ __forceinline__ float pair_dist(float rh, float ih, float rt, float it,
                                           float cr, float sr) {
    float re = fmaf(rh, cr, fmaf(-ih, sr, -rt));
    float im = fmaf(rh, sr, fmaf(ih, cr, -it));
    return sqrtf(fmaf(re, re, im * im));
}

// One warp per (permuted) edge. Edges are sorted by head bucket, so the heads
// touched by concurrently-resident warps span only a few MB -> L1/L2 hot.
__global__ void __launch_bounds__(256)
rotate_score_kernel(const float* __restrict__ nodes,
                    const float* __restrict__ temperature,
                    const float* __restrict__ bias,
                    float* __restrict__ out,
                    int num_edges) {
    int warp_id = (blockIdx.x * blockDim.x + threadIdx.x) >> 5;
    int lane = threadIdx.x & 31;
    if (warp_id >= num_edges) return;

    int4 w = g_perm[warp_id];
    long long h = w.x;
    long long t = w.y;
    int r = w.z;

    const float4* __restrict__ hp = (const float4*)(nodes + h * (long long)DIM);
    const float4* __restrict__ tp = (const float4*)(nodes + t * (long long)DIM);
    const float4* __restrict__ cp = (const float4*)(g_cosT + r * HALF);
    const float4* __restrict__ sp = (const float4*)(g_sinT + r * HALF);

    float acc = 0.0f;

    #pragma unroll
    for (int k = 0; k < 2; k++) {
        int j = lane + k * 32;

        float4 rh = hp[j];
        float4 ih = hp[j + 64];
        float4 rt = tp[j];
        float4 it = tp[j + 64];
        float4 cr = cp[j];
        float4 sr = sp[j];

        acc += pair_dist(rh.x, ih.x, rt.x, it.x, cr.x, sr.x);
        acc += pair_dist(rh.y, ih.y, rt.y, it.y, cr.y, sr.y);
        acc += pair_dist(rh.z, ih.z, rt.z, it.z, cr.z, sr.z);
        acc += pair_dist(rh.w, ih.w, rt.w, it.w, cr.w, sr.w);
    }

    #pragma unroll
    for (int off = 16; off > 0; off >>= 1)
        acc += __shfl_down_sync(0xffffffffu, acc, off);

    if (lane == 0) {
        float mean = acc * (1.0f / (float)HALF);
        out[w.w] = -(mean / temperature[0]) + bias[0];
    }
}

extern "C" void kernel_launch(void* const* d_in, const int* in_sizes, int n_in,
                              void* d_out, int out_size) {
    const float* nodes       = (const float*)d_in[0];
    const int*   edge_index  = (const int*)d_in[1];
    const int*   rel_type    = (const int*)d_in[2];
    const float* rel_emb     = (const float*)d_in[3];
    const float* temperature = (const float*)d_in[4];
    const float* bias        = (const float*)d_in[5];
    float*       out         = (float*)d_out;

    int num_edges = in_sizes[2];
    int num_nodes = in_sizes[0] / DIM;

    precompute_rot_kernel<<<(NUM_REL * HALF + 255) / 256, 256>>>(rel_emb);

    // Counting sort of edges by head bucket
    zero_count_kernel<<<(NB + 255) / 256, 256>>>();
    hist_kernel<<<(num_edges + 255) / 256, 256>>>(edge_index, num_edges, num_nodes);
    scan_kernel<<<1, NB>>>();
    scatter_kernel<<<(num_edges + 255) / 256, 256>>>(edge_index, rel_type,
                                                     num_edges, num_nodes);

    int warps_per_block = 256 / 32;
    int blocks = (num_edges + warps_per_block - 1) / warps_per_block;
    rotate_score_kernel<<<blocks, 256>>>(nodes, temperature, bias, out, num_edges);
}

// round 4
// speedup vs baseline: 1.3795x; 1.3795x over previous
#include <cuda_runtime.h>
#include <cuda_fp16.h>
#include <math.h>

#define PI_F 3.14159265358979323846f
#define MARGIN_F 9.0f

#define DIM 512
#define HALF 256
#define NUM_REL 64
#define MAX_NODES 100000

// Precomputed rotation tables: 64 relations x 256 dims of cos/sin (128 KB).
__device__ float g_cosT[NUM_REL * HALF];
__device__ float g_sinT[NUM_REL * HALF];

// fp16 copy of the node table: 100000 x 512 halfs = 102.4 MB.
// Fits in GB300's ~126 MB L2 -> random gather served from L2, not HBM.
__device__ __half g_nodesH[(size_t)MAX_NODES * DIM];

__global__ void precompute_rot_kernel(const float* __restrict__ relation_emb) {
    int i = blockIdx.x * blockDim.x + threadIdx.x;
    if (i < NUM_REL * HALF) {
        float phase = relation_emb[i] * (PI_F / MARGIN_F);
        float s, c;
        sincosf(phase, &s, &c);
        g_cosT[i] = c;
        g_sinT[i] = s;
    }
}

// Convert fp32 node table -> fp16. Processes 8 floats -> 8 halfs per thread.
__global__ void __launch_bounds__(256)
convert_nodes_kernel(const float* __restrict__ nodes, long long n_elems8) {
    long long i = (long long)blockIdx.x * blockDim.x + threadIdx.x;
    if (i >= n_elems8) return;
    const float4* src = (const float4*)nodes;
    float4 a = src[i * 2];
    float4 b = src[i * 2 + 1];
    __half2 h0 = __floats2half2_rn(a.x, a.y);
    __half2 h1 = __floats2half2_rn(a.z, a.w);
    __half2 h2 = __floats2half2_rn(b.x, b.y);
    __half2 h3 = __floats2half2_rn(b.z, b.w);
    uint4 packed;
    packed.x = *(unsigned*)&h0;
    packed.y = *(unsigned*)&h1;
    packed.z = *(unsigned*)&h2;
    packed.w = *(unsigned*)&h3;
    ((uint4*)g_nodesH)[i] = packed;
}

__device__ __forceinline__ float pair_dist(float rh, float ih, float rt, float it,
                                           float cr, float sr) {
    float re = fmaf(rh, cr, fmaf(-ih, sr, -rt));
    float im = fmaf(rh, sr, fmaf(ih, cr, -it));
    return sqrtf(fmaf(re, re, im * im));
}

// One warp per edge. Each lane handles 8 consecutive elements of the 256-wide
// half: one 16B (8 x half) load per operand stream -> each warp load = one
// perfectly coalesced 512B segment. 4 node loads/edge = 2KB logical traffic.
__global__ void __launch_bounds__(256)
rotate_score_kernel(const int* __restrict__ edge_index,
                    const int* __restrict__ rel_type,
                    const float* __restrict__ temperature,
                    const float* __restrict__ bias,
                    float* __restrict__ out,
                    int num_edges) {
    int warp_id = (blockIdx.x * blockDim.x + threadIdx.x) >> 5;
    int lane = threadIdx.x & 31;
    if (warp_id >= num_edges) return;

    long long h = (long long)edge_index[warp_id];
    long long t = (long long)edge_index[num_edges + warp_id];
    int r = rel_type[warp_id];

    const uint4* __restrict__ hp = (const uint4*)(g_nodesH + h * DIM);
    const uint4* __restrict__ tp = (const uint4*)(g_nodesH + t * DIM);
    const float4* __restrict__ cp = (const float4*)(g_cosT + r * HALF);
    const float4* __restrict__ sp = (const float4*)(g_sinT + r * HALF);

    // 8 halfs per 16B load; re = elems [0,256), im = elems [256,512)
    uint4 rhu = hp[lane];        // re_head [lane*8 .. lane*8+8)
    uint4 ihu = hp[lane + 32];   // im_head
    uint4 rtu = tp[lane];        // re_tail
    uint4 itu = tp[lane + 32];   // im_tail
    float4 cr0 = cp[lane * 2];
    float4 cr1 = cp[lane * 2 + 1];
    float4 sr0 = sp[lane * 2];
    float4 sr1 = sp[lane * 2 + 1];

    const unsigned* rh_w = &rhu.x;
    const unsigned* ih_w = &ihu.x;
    const unsigned* rt_w = &rtu.x;
    const unsigned* it_w = &itu.x;
    const float* crf = &cr0.x;   // cr0,cr1 are contiguous in regs via array view
    const float* srf = &sr0.x;

    float cr_arr[8] = {cr0.x, cr0.y, cr0.z, cr0.w, cr1.x, cr1.y, cr1.z, cr1.w};
    float sr_arr[8] = {sr0.x, sr0.y, sr0.z, sr0.w, sr1.x, sr1.y, sr1.z, sr1.w};
    (void)crf; (void)srf;

    float acc = 0.0f;
    #pragma unroll
    for (int w = 0; w < 4; w++) {
        float2 rh = __half22float2(*(const __half2*)&rh_w[w]);
        float2 ih = __half22float2(*(const __half2*)&ih_w[w]);
        float2 rt = __half22float2(*(const __half2*)&rt_w[w]);
        float2 it = __half22float2(*(const __half2*)&it_w[w]);
        acc += pair_dist(rh.x, ih.x, rt.x, it.x, cr_arr[w * 2],     sr_arr[w * 2]);
        acc += pair_dist(rh.y, ih.y, rt.y, it.y, cr_arr[w * 2 + 1], sr_arr[w * 2 + 1]);
    }

    #pragma unroll
    for (int off = 16; off > 0; off >>= 1)
        acc += __shfl_down_sync(0xffffffffu, acc, off);

    if (lane == 0) {
        float mean = acc * (1.0f / (float)HALF);
        out[warp_id] = -(mean / temperature[0]) + bias[0];
    }
}

extern "C" void kernel_launch(void* const* d_in, const int* in_sizes, int n_in,
                              void* d_out, int out_size) {
    const float* nodes       = (const float*)d_in[0];
    const int*   edge_index  = (const int*)d_in[1];
    const int*   rel_type    = (const int*)d_in[2];
    const float* rel_emb     = (const float*)d_in[3];
    const float* temperature = (const float*)d_in[4];
    const float* bias        = (const float*)d_in[5];
    float*       out         = (float*)d_out;

    int num_edges = in_sizes[2];
    long long n_nodes_elems = (long long)in_sizes[0];
    long long n_elems8 = n_nodes_elems / 8;

    precompute_rot_kernel<<<(NUM_REL * HALF + 255) / 256, 256>>>(rel_emb);
    convert_nodes_kernel<<<(int)((n_elems8 + 255) / 256), 256>>>(nodes, n_elems8);

    int warps_per_block = 256 / 32;
    int blocks = (num_edges + warps_per_block - 1) / warps_per_block;
    rotate_score_kernel<<<blocks, 256>>>(edge_index, rel_type,
                                         temperature, bias, out, num_edges);
}

// round 6
// speedup vs baseline: 1.3901x; 1.0076x over previous
#include <cuda_runtime.h>
#include <cuda_fp16.h>
#include <math.h>

#define PI_F 3.14159265358979323846f
#define MARGIN_F 9.0f

#define DIM 512
#define HALF 256
#define NUM_REL 64
#define MAX_NODES 100000
#define ROT_BLOCKS 64   // first 64 blocks of prep kernel build the rot tables

// Precomputed rotation tables: 64 relations x 256 dims of cos/sin (128 KB).
__device__ float g_cosT[NUM_REL * HALF];
__device__ float g_sinT[NUM_REL * HALF];

// fp16 copy of the node table: 100000 x 512 halfs = 102.4 MB.
__device__ __half g_nodesH[(size_t)MAX_NODES * DIM];

// ---- eviction-hinted memory ops (createpolicy + cache_hint form) ----
__device__ __forceinline__ uint4 ldg_evict_last(const uint4* p) {
    uint4 v;
    asm("{\n\t"
        ".reg .b64 pol;\n\t"
        "createpolicy.fractional.L2::evict_last.b64 pol, 1.0;\n\t"
        "ld.global.L2::cache_hint.v4.u32 {%0,%1,%2,%3}, [%4], pol;\n\t"
        "}"
        : "=r"(v.x), "=r"(v.y), "=r"(v.z), "=r"(v.w) : "l"(p));
    return v;
}
__device__ __forceinline__ void stg_evict_last(uint4* p, uint4 v) {
    asm volatile("{\n\t"
        ".reg .b64 pol;\n\t"
        "createpolicy.fractional.L2::evict_last.b64 pol, 1.0;\n\t"
        "st.global.L2::cache_hint.v4.u32 [%0], {%1,%2,%3,%4}, pol;\n\t"
        "}"
        :: "l"(p), "r"(v.x), "r"(v.y), "r"(v.z), "r"(v.w) : "memory");
}
__device__ __forceinline__ float4 ldg_streaming_f4(const float4* p) {
    float4 v;
    asm("ld.global.cs.v4.f32 {%0,%1,%2,%3}, [%4];"
        : "=f"(v.x), "=f"(v.y), "=f"(v.z), "=f"(v.w) : "l"(p));
    return v;
}

// Fused prep: blocks [0,ROT_BLOCKS) build cos/sin tables; the rest convert
// the fp32 node table to fp16 (8 floats -> 8 halfs per thread).
// fp32 source is loaded streaming (evict-first); fp16 table stored evict-last
// so it claims L2 residency for the gather kernel.
__global__ void __launch_bounds__(256)
prep_kernel(const float* __restrict__ relation_emb,
            const float* __restrict__ nodes,
            long long n_elems8) {
    if (blockIdx.x < ROT_BLOCKS) {
        int i = blockIdx.x * blockDim.x + threadIdx.x;
        if (i < NUM_REL * HALF) {
            float phase = relation_emb[i] * (PI_F / MARGIN_F);
            float s, c;
            sincosf(phase, &s, &c);
            g_cosT[i] = c;
            g_sinT[i] = s;
        }
        return;
    }
    long long i = (long long)(blockIdx.x - ROT_BLOCKS) * blockDim.x + threadIdx.x;
    if (i >= n_elems8) return;
    const float4* src = (const float4*)nodes;
    float4 a = ldg_streaming_f4(&src[i * 2]);
    float4 b = ldg_streaming_f4(&src[i * 2 + 1]);
    __half2 h0 = __floats2half2_rn(a.x, a.y);
    __half2 h1 = __floats2half2_rn(a.z, a.w);
    __half2 h2 = __floats2half2_rn(b.x, b.y);
    __half2 h3 = __floats2half2_rn(b.z, b.w);
    uint4 packed;
    packed.x = *(unsigned*)&h0;
    packed.y = *(unsigned*)&h1;
    packed.z = *(unsigned*)&h2;
    packed.w = *(unsigned*)&h3;
    stg_evict_last(&((uint4*)g_nodesH)[i], packed);
}

__device__ __forceinline__ float pair_dist(float rh, float ih, float rt, float it,
                                           float cr, float sr) {
    float re = fmaf(rh, cr, fmaf(-ih, sr, -rt));
    float im = fmaf(rh, sr, fmaf(ih, cr, -it));
    return sqrtf(fmaf(re, re, im * im));
}

// One warp per edge; 2KB of fp16 node data per edge in 4 coalesced 512B
// segments, all loaded with L2 evict-last so the table stays resident.
__global__ void __launch_bounds__(256)
rotate_score_kernel(const int* __restrict__ edge_index,
                    const int* __restrict__ rel_type,
                    const float* __restrict__ temperature,
                    const float* __restrict__ bias,
                    float* __restrict__ out,
                    int num_edges) {
    int warp_id = (blockIdx.x * blockDim.x + threadIdx.x) >> 5;
    int lane = threadIdx.x & 31;
    if (warp_id >= num_edges) return;

    long long h = (long long)edge_index[warp_id];
    long long t = (long long)edge_index[num_edges + warp_id];
    int r = rel_type[warp_id];

    const uint4* __restrict__ hp = (const uint4*)(g_nodesH + h * DIM);
    const uint4* __restrict__ tp = (const uint4*)(g_nodesH + t * DIM);
    const float4* __restrict__ cp = (const float4*)(g_cosT + r * HALF);
    const float4* __restrict__ sp = (const float4*)(g_sinT + r * HALF);

    uint4 rhu = ldg_evict_last(&hp[lane]);        // re_head
    uint4 ihu = ldg_evict_last(&hp[lane + 32]);   // im_head
    uint4 rtu = ldg_evict_last(&tp[lane]);        // re_tail
    uint4 itu = ldg_evict_last(&tp[lane + 32]);   // im_tail
    float4 cr0 = cp[lane * 2];
    float4 cr1 = cp[lane * 2 + 1];
    float4 sr0 = sp[lane * 2];
    float4 sr1 = sp[lane * 2 + 1];

    const unsigned* rh_w = &rhu.x;
    const unsigned* ih_w = &ihu.x;
    const unsigned* rt_w = &rtu.x;
    const unsigned* it_w = &itu.x;
    float cr_arr[8] = {cr0.x, cr0.y, cr0.z, cr0.w, cr1.x, cr1.y, cr1.z, cr1.w};
    float sr_arr[8] = {sr0.x, sr0.y, sr0.z, sr0.w, sr1.x, sr1.y, sr1.z, sr1.w};

    float acc = 0.0f;
    #pragma unroll
    for (int w = 0; w < 4; w++) {
        float2 rh = __half22float2(*(const __half2*)&rh_w[w]);
        float2 ih = __half22float2(*(const __half2*)&ih_w[w]);
        float2 rt = __half22float2(*(const __half2*)&rt_w[w]);
        float2 it = __half22float2(*(const __half2*)&it_w[w]);
        acc += pair_dist(rh.x, ih.x, rt.x, it.x, cr_arr[w * 2],     sr_arr[w * 2]);
        acc += pair_dist(rh.y, ih.y, rt.y, it.y, cr_arr[w * 2 + 1], sr_arr[w * 2 + 1]);
    }

    #pragma unroll
    for (int off = 16; off > 0; off >>= 1)
        acc += __shfl_down_sync(0xffffffffu, acc, off);

    if (lane == 0) {
        float mean = acc * (1.0f / (float)HALF);
        out[warp_id] = -(mean / temperature[0]) + bias[0];
    }
}

extern "C" void kernel_launch(void* const* d_in, const int* in_sizes, int n_in,
                              void* d_out, int out_size) {
    const float* nodes       = (const float*)d_in[0];
    const int*   edge_index  = (const int*)d_in[1];
    const int*   rel_type    = (const int*)d_in[2];
    const float* rel_emb     = (const float*)d_in[3];
    const float* temperature = (const float*)d_in[4];
    const float* bias        = (const float*)d_in[5];
    float*       out         = (float*)d_out;

    int num_edges = in_sizes[2];
    long long n_elems8 = (long long)in_sizes[0] / 8;

    int conv_blocks = (int)((n_elems8 + 255) / 256);
    prep_kernel<<<ROT_BLOCKS + conv_blocks, 256>>>(rel_emb, nodes, n_elems8);

    int warps_per_block = 256 / 32;
    int blocks = (num_edges + warps_per_block - 1) / warps_per_block;
    rotate_score_kernel<<<blocks, 256>>>(edge_index, rel_type,
                                         temperature, bias, out, num_edges);
}

// round 7
// speedup vs baseline: 2.2771x; 1.6381x over previous
#include <cuda_runtime.h>
#include <cuda_fp16.h>
#include <math.h>

#define PI_F 3.14159265358979323846f
#define MARGIN_F 9.0f

#define DIM 512
#define HALF 256
#define NUM_REL 64
#define MAX_NODES 100000
#define ROT_BLOCKS 64   // first 64 blocks of prep kernel build the rot tables

// fp16 rotation tables: 64 relations x 256 dims (32 KB each) — L2/L1 hot.
__device__ __half g_cosH[NUM_REL * HALF];
__device__ __half g_sinH[NUM_REL * HALF];

// fp16 copy of the node table: 100000 x 512 halfs = 102.4 MB (fits in L2).
__device__ __half g_nodesH[(size_t)MAX_NODES * DIM];

// ---- eviction-hinted memory ops (createpolicy + cache_hint form) ----
__device__ __forceinline__ uint4 ldg_evict_last(const uint4* p) {
    uint4 v;
    asm("{\n\t"
        ".reg .b64 pol;\n\t"
        "createpolicy.fractional.L2::evict_last.b64 pol, 1.0;\n\t"
        "ld.global.L2::cache_hint.v4.u32 {%0,%1,%2,%3}, [%4], pol;\n\t"
        "}"
        : "=r"(v.x), "=r"(v.y), "=r"(v.z), "=r"(v.w) : "l"(p));
    return v;
}
__device__ __forceinline__ void stg_evict_last(uint4* p, uint4 v) {
    asm volatile("{\n\t"
        ".reg .b64 pol;\n\t"
        "createpolicy.fractional.L2::evict_last.b64 pol, 1.0;\n\t"
        "st.global.L2::cache_hint.v4.u32 [%0], {%1,%2,%3,%4}, pol;\n\t"
        "}"
        :: "l"(p), "r"(v.x), "r"(v.y), "r"(v.z), "r"(v.w) : "memory");
}
__device__ __forceinline__ float4 ldg_streaming_f4(const float4* p) {
    float4 v;
    asm("ld.global.cs.v4.f32 {%0,%1,%2,%3}, [%4];"
        : "=f"(v.x), "=f"(v.y), "=f"(v.z), "=f"(v.w) : "l"(p));
    return v;
}
// Single-instruction MUFU sqrt (rel err ~1e-6), independent of compiler flags.
__device__ __forceinline__ float sqrt_approx(float x) {
    float r;
    asm("sqrt.approx.f32 %0, %1;" : "=f"(r) : "f"(x));
    return r;
}

// Fused prep: blocks [0,ROT_BLOCKS) build fp16 cos/sin tables; the rest
// convert the fp32 node table to fp16. fp32 source is loaded streaming
// (evict-first); fp16 table stored evict-last to claim L2 residency.
__global__ void __launch_bounds__(256)
prep_kernel(const float* __restrict__ relation_emb,
            const float* __restrict__ nodes,
            long long n_elems8) {
    if (blockIdx.x < ROT_BLOCKS) {
        int i = blockIdx.x * blockDim.x + threadIdx.x;
        if (i < NUM_REL * HALF) {
            float phase = relation_emb[i] * (PI_F / MARGIN_F);
            float s, c;
            sincosf(phase, &s, &c);
            g_cosH[i] = __float2half_rn(c);
            g_sinH[i] = __float2half_rn(s);
        }
        return;
    }
    long long i = (long long)(blockIdx.x - ROT_BLOCKS) * blockDim.x + threadIdx.x;
    if (i >= n_elems8) return;
    const float4* src = (const float4*)nodes;
    float4 a = ldg_streaming_f4(&src[i * 2]);
    float4 b = ldg_streaming_f4(&src[i * 2 + 1]);
    __half2 h0 = __floats2half2_rn(a.x, a.y);
    __half2 h1 = __floats2half2_rn(a.z, a.w);
    __half2 h2 = __floats2half2_rn(b.x, b.y);
    __half2 h3 = __floats2half2_rn(b.z, b.w);
    uint4 packed;
    packed.x = *(unsigned*)&h0;
    packed.y = *(unsigned*)&h1;
    packed.z = *(unsigned*)&h2;
    packed.w = *(unsigned*)&h3;
    stg_evict_last(&((uint4*)g_nodesH)[i], packed);
}

// One warp per edge; 2KB fp16 node data per edge in 4 coalesced 512B segments
// (evict-last). Rotation + squaring in packed HFMA2; fp32 only for sqrt+acc.
__global__ void __launch_bounds__(256)
rotate_score_kernel(const int* __restrict__ edge_index,
                    const int* __restrict__ rel_type,
                    const float* __restrict__ temperature,
                    const float* __restrict__ bias,
                    float* __restrict__ out,
                    int num_edges) {
    int warp_id = (blockIdx.x * blockDim.x + threadIdx.x) >> 5;
    int lane = threadIdx.x & 31;
    if (warp_id >= num_edges) return;

    long long h = (long long)edge_index[warp_id];
    long long t = (long long)edge_index[num_edges + warp_id];
    int r = rel_type[warp_id];

    const uint4* __restrict__ hp = (const uint4*)(g_nodesH + h * DIM);
    const uint4* __restrict__ tp = (const uint4*)(g_nodesH + t * DIM);

    uint4 rhu = ldg_evict_last(&hp[lane]);        // re_head: 8 halfs
    uint4 ihu = ldg_evict_last(&hp[lane + 32]);   // im_head
    uint4 rtu = ldg_evict_last(&tp[lane]);        // re_tail
    uint4 itu = ldg_evict_last(&tp[lane + 32]);   // im_tail
    uint4 cru = *(const uint4*)(g_cosH + r * HALF + lane * 8);
    uint4 sru = *(const uint4*)(g_sinH + r * HALF + lane * 8);

    const unsigned* rh_w = &rhu.x;
    const unsigned* ih_w = &ihu.x;
    const unsigned* rt_w = &rtu.x;
    const unsigned* it_w = &itu.x;
    const unsigned* cr_w = &cru.x;
    const unsigned* sr_w = &sru.x;

    float acc = 0.0f;
    #pragma unroll
    for (int w = 0; w < 4; w++) {
        __half2 rh2 = *(const __half2*)&rh_w[w];
        __half2 ih2 = *(const __half2*)&ih_w[w];
        __half2 rt2 = *(const __half2*)&rt_w[w];
        __half2 it2 = *(const __half2*)&it_w[w];
        __half2 cr2 = *(const __half2*)&cr_w[w];
        __half2 sr2 = *(const __half2*)&sr_w[w];

        // re = rh*cr - ih*sr - rt ; im = rh*sr + ih*cr - it  (packed x2)
        __half2 re2 = __hfma2(rh2, cr2, __hfma2(__hneg2(ih2), sr2, __hneg2(rt2)));
        __half2 im2 = __hfma2(rh2, sr2, __hfma2(ih2, cr2, __hneg2(it2)));
        __half2 d2  = __hfma2(re2, re2, __hmul2(im2, im2));

        float2 d = __half22float2(d2);
        acc += sqrt_approx(d.x);
        acc += sqrt_approx(d.y);
    }

    #pragma unroll
    for (int off = 16; off > 0; off >>= 1)
        acc += __shfl_down_sync(0xffffffffu, acc, off);

    if (lane == 0) {
        float mean = acc * (1.0f / (float)HALF);
        out[warp_id] = -(mean / temperature[0]) + bias[0];
    }
}

extern "C" void kernel_launch(void* const* d_in, const int* in_sizes, int n_in,
                              void* d_out, int out_size) {
    const float* nodes       = (const float*)d_in[0];
    const int*   edge_index  = (const int*)d_in[1];
    const int*   rel_type    = (const int*)d_in[2];
    const float* rel_emb     = (const float*)d_in[3];
    const float* temperature = (const float*)d_in[4];
    const float* bias        = (const float*)d_in[5];
    float*       out         = (float*)d_out;

    int num_edges = in_sizes[2];
    long long n_elems8 = (long long)in_sizes[0] / 8;

    int conv_blocks = (int)((n_elems8 + 255) / 256);
    prep_kernel<<<ROT_BLOCKS + conv_blocks, 256>>>(rel_emb, nodes, n_elems8);

    int warps_per_block = 256 / 32;
    int blocks = (num_edges + warps_per_block - 1) / warps_per_block;
    rotate_score_kernel<<<blocks, 256>>>(edge_index, rel_type,
                                         temperature, bias, out, num_edges);
}

// round 8
// speedup vs baseline: 2.3695x; 1.0406x over previous
#include <cuda_runtime.h>
#include <cuda_fp16.h>
#include <math.h>

#define PI_F 3.14159265358979323846f
#define MARGIN_F 9.0f

#define DIM 512
#define HALF 256
#define NUM_REL 64
#define MAX_NODES 100000
#define ROT_BLOCKS 64   // first 64 blocks of prep kernel build the rot tables

// fp16 rotation tables: 64 relations x 256 dims (32 KB each) — L1/L2 hot.
__device__ __half g_cosH[NUM_REL * HALF];
__device__ __half g_sinH[NUM_REL * HALF];

// fp16 copy of the node table: 100000 x 512 halfs = 102.4 MB (L2-resident).
__device__ __half g_nodesH[(size_t)MAX_NODES * DIM];

// Precomputed epilogue constants: out = fmaf(acc, g_scale, g_bias)
__device__ float g_scale;
__device__ float g_bias;

// ---- eviction-hinted memory ops ----
__device__ __forceinline__ unsigned long long mk_evict_last_policy() {
    unsigned long long p;
    asm("createpolicy.fractional.L2::evict_last.b64 %0, 1.0;" : "=l"(p));
    return p;
}
__device__ __forceinline__ uint4 ldg_hint(const uint4* p, unsigned long long pol) {
    uint4 v;
    asm("ld.global.L2::cache_hint.v4.u32 {%0,%1,%2,%3}, [%4], %5;"
        : "=r"(v.x), "=r"(v.y), "=r"(v.z), "=r"(v.w) : "l"(p), "l"(pol));
    return v;
}
__device__ __forceinline__ void stg_hint(uint4* p, uint4 v, unsigned long long pol) {
    asm volatile("st.global.L2::cache_hint.v4.u32 [%0], {%1,%2,%3,%4}, %5;"
        :: "l"(p), "r"(v.x), "r"(v.y), "r"(v.z), "r"(v.w), "l"(pol) : "memory");
}
__device__ __forceinline__ float4 ldg_streaming_f4(const float4* p) {
    float4 v;
    asm("ld.global.cs.v4.f32 {%0,%1,%2,%3}, [%4];"
        : "=f"(v.x), "=f"(v.y), "=f"(v.z), "=f"(v.w) : "l"(p));
    return v;
}
// Single-instruction MUFU sqrt (rel err ~1e-6).
__device__ __forceinline__ float sqrt_approx(float x) {
    float r;
    asm("sqrt.approx.f32 %0, %1;" : "=f"(r) : "f"(x));
    return r;
}

// Fused prep: blocks [0,ROT_BLOCKS) build fp16 cos/sin tables (+ scalar
// epilogue constants); the rest convert the fp32 node table to fp16.
__global__ void __launch_bounds__(256)
prep_kernel(const float* __restrict__ relation_emb,
            const float* __restrict__ nodes,
            const float* __restrict__ temperature,
            const float* __restrict__ bias,
            long long n_elems8) {
    if (blockIdx.x < ROT_BLOCKS) {
        int i = blockIdx.x * blockDim.x + threadIdx.x;
        if (i == 0) {
            g_scale = -1.0f / ((float)HALF * temperature[0]);
            g_bias  = bias[0];
        }
        if (i < NUM_REL * HALF) {
            float phase = relation_emb[i] * (PI_F / MARGIN_F);
            float s, c;
            sincosf(phase, &s, &c);
            g_cosH[i] = __float2half_rn(c);
            g_sinH[i] = __float2half_rn(s);
        }
        return;
    }
    long long i = (long long)(blockIdx.x - ROT_BLOCKS) * blockDim.x + threadIdx.x;
    if (i >= n_elems8) return;
    unsigned long long pol = mk_evict_last_policy();
    const float4* src = (const float4*)nodes;
    float4 a = ldg_streaming_f4(&src[i * 2]);
    float4 b = ldg_streaming_f4(&src[i * 2 + 1]);
    __half2 h0 = __floats2half2_rn(a.x, a.y);
    __half2 h1 = __floats2half2_rn(a.z, a.w);
    __half2 h2 = __floats2half2_rn(b.x, b.y);
    __half2 h3 = __floats2half2_rn(b.z, b.w);
    uint4 packed;
    packed.x = *(unsigned*)&h0;
    packed.y = *(unsigned*)&h1;
    packed.z = *(unsigned*)&h2;
    packed.w = *(unsigned*)&h3;
    stg_hint(&((uint4*)g_nodesH)[i], packed, pol);
}

// One warp per edge; 2KB fp16 node data per edge in 4 coalesced 512B segments
// (evict-last, policy hoisted). Rotation + squaring packed HFMA2; f32 sqrt+acc.
__global__ void __launch_bounds__(256)
rotate_score_kernel(const int* __restrict__ edge_index,
                    const int* __restrict__ rel_type,
                    float* __restrict__ out,
                    int num_edges) {
    int warp_id = (blockIdx.x * blockDim.x + threadIdx.x) >> 5;
    int lane = threadIdx.x & 31;
    if (warp_id >= num_edges) return;

    long long h = (long long)edge_index[warp_id];
    long long t = (long long)edge_index[num_edges + warp_id];
    int r = rel_type[warp_id];

    unsigned long long pol = mk_evict_last_policy();

    const uint4* __restrict__ hp = (const uint4*)(g_nodesH + (h << 9));
    const uint4* __restrict__ tp = (const uint4*)(g_nodesH + (t << 9));

    uint4 rhu = ldg_hint(&hp[lane], pol);        // re_head: 8 halfs
    uint4 ihu = ldg_hint(&hp[lane + 32], pol);   // im_head
    uint4 rtu = ldg_hint(&tp[lane], pol);        // re_tail
    uint4 itu = ldg_hint(&tp[lane + 32], pol);   // im_tail
    uint4 cru = *(const uint4*)(g_cosH + r * HALF + lane * 8);
    uint4 sru = *(const uint4*)(g_sinH + r * HALF + lane * 8);

    const unsigned* rh_w = &rhu.x;
    const unsigned* ih_w = &ihu.x;
    const unsigned* rt_w = &rtu.x;
    const unsigned* it_w = &itu.x;
    const unsigned* cr_w = &cru.x;
    const unsigned* sr_w = &sru.x;

    float acc0 = 0.0f, acc1 = 0.0f;
    #pragma unroll
    for (int w = 0; w < 4; w++) {
        __half2 rh2 = *(const __half2*)&rh_w[w];
        __half2 ih2 = *(const __half2*)&ih_w[w];
        __half2 rt2 = *(const __half2*)&rt_w[w];
        __half2 it2 = *(const __half2*)&it_w[w];
        __half2 cr2 = *(const __half2*)&cr_w[w];
        __half2 sr2 = *(const __half2*)&sr_w[w];

        // re = rh*cr - (ih*sr + rt) ; im = rh*sr + (ih*cr - it)
        __half2 wv  = __hfma2(ih2, sr2, rt2);
        __half2 re2 = __hfma2(rh2, cr2, __hneg2(wv));
        __half2 im2 = __hfma2(rh2, sr2, __hfma2(ih2, cr2, __hneg2(it2)));
        __half2 d2  = __hfma2(re2, re2, __hmul2(im2, im2));

        float2 d = __half22float2(d2);
        acc0 += sqrt_approx(d.x);
        acc1 += sqrt_approx(d.y);
    }

    float acc = acc0 + acc1;
    #pragma unroll
    for (int off = 16; off > 0; off >>= 1)
        acc += __shfl_down_sync(0xffffffffu, acc, off);

    if (lane == 0)
        out[warp_id] = fmaf(acc, g_scale, g_bias);
}

extern "C" void kernel_launch(void* const* d_in, const int* in_sizes, int n_in,
                              void* d_out, int out_size) {
    const float* nodes       = (const float*)d_in[0];
    const int*   edge_index  = (const int*)d_in[1];
    const int*   rel_type    = (const int*)d_in[2];
    const float* rel_emb     = (const float*)d_in[3];
    const float* temperature = (const float*)d_in[4];
    const float* bias        = (const float*)d_in[5];
    float*       out         = (float*)d_out;

    int num_edges = in_sizes[2];
    long long n_elems8 = (long long)in_sizes[0] / 8;

    int conv_blocks = (int)((n_elems8 + 255) / 256);
    prep_kernel<<<ROT_BLOCKS + conv_blocks, 256>>>(rel_emb, nodes,
                                                   temperature, bias, n_elems8);

    int warps_per_block = 256 / 32;
    int blocks = (num_edges + warps_per_block - 1) / warps_per_block;
    rotate_score_kernel<<<blocks, 256>>>(edge_index, rel_type, out, num_edges);
}

// round 9
// speedup vs baseline: 2.5125x; 1.0604x over previous
#include <cuda_runtime.h>
#include <cuda_fp16.h>
#include <math.h>

#define PI_F 3.14159265358979323846f
#define MARGIN_F 9.0f

#define DIM 512
#define HALF 256
#define NUM_REL 64
#define MAX_NODES 100000
#define ROT_BLOCKS 64   // first 64 blocks of prep kernel build the rot tables

// fp16 rotation tables: 64 relations x 256 dims (32 KB each) — L1/L2 hot.
__device__ __half g_cosH[NUM_REL * HALF];
__device__ __half g_sinH[NUM_REL * HALF];

// fp16 copy of the node table: 100000 x 512 halfs = 102.4 MB (L2-resident).
__device__ __half g_nodesH[(size_t)MAX_NODES * DIM];

// Precomputed epilogue constants: out = fmaf(acc, g_scale, g_bias)
__device__ float g_scale;
__device__ float g_bias;

// ---- eviction-hinted memory ops ----
__device__ __forceinline__ unsigned long long mk_evict_last_policy() {
    unsigned long long p;
    asm("createpolicy.fractional.L2::evict_last.b64 %0, 1.0;" : "=l"(p));
    return p;
}
__device__ __forceinline__ uint4 ldg_hint(const uint4* p, unsigned long long pol) {
    uint4 v;
    asm("ld.global.L2::cache_hint.v4.u32 {%0,%1,%2,%3}, [%4], %5;"
        : "=r"(v.x), "=r"(v.y), "=r"(v.z), "=r"(v.w) : "l"(p), "l"(pol));
    return v;
}
__device__ __forceinline__ void stg_hint(uint4* p, uint4 v, unsigned long long pol) {
    asm volatile("st.global.L2::cache_hint.v4.u32 [%0], {%1,%2,%3,%4}, %5;"
        :: "l"(p), "r"(v.x), "r"(v.y), "r"(v.z), "r"(v.w), "l"(pol) : "memory");
}
__device__ __forceinline__ float4 ldg_streaming_f4(const float4* p) {
    float4 v;
    asm("ld.global.cs.v4.f32 {%0,%1,%2,%3}, [%4];"
        : "=f"(v.x), "=f"(v.y), "=f"(v.z), "=f"(v.w) : "l"(p));
    return v;
}
__device__ __forceinline__ float sqrt_approx(float x) {
    float r;
    asm("sqrt.approx.f32 %0, %1;" : "=f"(r) : "f"(x));
    return r;
}

// Fused prep kernel (unchanged from R8).
__global__ void __launch_bounds__(256)
prep_kernel(const float* __restrict__ relation_emb,
            const float* __restrict__ nodes,
            const float* __restrict__ temperature,
            const float* __restrict__ bias,
            long long n_elems8) {
    if (blockIdx.x < ROT_BLOCKS) {
        int i = blockIdx.x * blockDim.x + threadIdx.x;
        if (i == 0) {
            g_scale = -1.0f / ((float)HALF * temperature[0]);
            g_bias  = bias[0];
        }
        if (i < NUM_REL * HALF) {
            float phase = relation_emb[i] * (PI_F / MARGIN_F);
            float s, c;
            sincosf(phase, &s, &c);
            g_cosH[i] = __float2half_rn(c);
            g_sinH[i] = __float2half_rn(s);
        }
        return;
    }
    long long i = (long long)(blockIdx.x - ROT_BLOCKS) * blockDim.x + threadIdx.x;
    if (i >= n_elems8) return;
    unsigned long long pol = mk_evict_last_policy();
    const float4* src = (const float4*)nodes;
    float4 a = ldg_streaming_f4(&src[i * 2]);
    float4 b = ldg_streaming_f4(&src[i * 2 + 1]);
    __half2 h0 = __floats2half2_rn(a.x, a.y);
    __half2 h1 = __floats2half2_rn(a.z, a.w);
    __half2 h2 = __floats2half2_rn(b.x, b.y);
    __half2 h3 = __floats2half2_rn(b.z, b.w);
    uint4 packed;
    packed.x = *(unsigned*)&h0;
    packed.y = *(unsigned*)&h1;
    packed.z = *(unsigned*)&h2;
    packed.w = *(unsigned*)&h3;
    stg_hint(&((uint4*)g_nodesH)[i], packed, pol);
}

// Accumulate one edge's partial distance sum for this lane (8 elems).
__device__ __forceinline__ float edge_partial(long long h, long long t, int r,
                                              int lane, unsigned long long pol) {
    const uint4* hp = (const uint4*)(g_nodesH + (h << 9));
    const uint4* tp = (const uint4*)(g_nodesH + (t << 9));

    uint4 rhu = ldg_hint(&hp[lane], pol);
    uint4 ihu = ldg_hint(&hp[lane + 32], pol);
    uint4 rtu = ldg_hint(&tp[lane], pol);
    uint4 itu = ldg_hint(&tp[lane + 32], pol);
    uint4 cru = *(const uint4*)(g_cosH + r * HALF + lane * 8);
    uint4 sru = *(const uint4*)(g_sinH + r * HALF + lane * 8);

    const unsigned* rh_w = &rhu.x;
    const unsigned* ih_w = &ihu.x;
    const unsigned* rt_w = &rtu.x;
    const unsigned* it_w = &itu.x;
    const unsigned* cr_w = &cru.x;
    const unsigned* sr_w = &sru.x;

    float a0 = 0.0f, a1 = 0.0f;
    #pragma unroll
    for (int w = 0; w < 4; w++) {
        __half2 rh2 = *(const __half2*)&rh_w[w];
        __half2 ih2 = *(const __half2*)&ih_w[w];
        __half2 rt2 = *(const __half2*)&rt_w[w];
        __half2 it2 = *(const __half2*)&it_w[w];
        __half2 cr2 = *(const __half2*)&cr_w[w];
        __half2 sr2 = *(const __half2*)&sr_w[w];

        __half2 wv  = __hfma2(ih2, sr2, rt2);
        __half2 re2 = __hfma2(rh2, cr2, __hneg2(wv));
        __half2 im2 = __hfma2(rh2, sr2, __hfma2(ih2, cr2, __hneg2(it2)));
        __half2 d2  = __hfma2(re2, re2, __hmul2(im2, im2));

        float2 d = __half22float2(d2);
        a0 += sqrt_approx(d.x);
        a1 += sqrt_approx(d.y);
    }
    return a0 + a1;
}

// Two edges per warp. Paired butterfly reduction: 5 shuffles for both edges.
__global__ void __launch_bounds__(256)
rotate_score_kernel(const int* __restrict__ edge_index,
                    const int* __restrict__ rel_type,
                    float* __restrict__ out,
                    int num_edges) {
    int wp = (blockIdx.x * blockDim.x + threadIdx.x) >> 5;   // warp = edge pair
    int lane = threadIdx.x & 31;
    int e0 = wp * 2;
    if (e0 >= num_edges) return;
    bool hasB = (e0 + 1) < num_edges;

    int hA, hB, tA, tB, rA, rB;
    if (hasB) {
        int2 hh = ((const int2*)edge_index)[wp];
        int2 tt = ((const int2*)(edge_index + num_edges))[wp];
        int2 rr = ((const int2*)rel_type)[wp];
        hA = hh.x; hB = hh.y; tA = tt.x; tB = tt.y; rA = rr.x; rB = rr.y;
    } else {
        hA = edge_index[e0]; tA = edge_index[num_edges + e0]; rA = rel_type[e0];
        hB = hA; tB = tA; rB = rA;
    }

    unsigned long long pol = mk_evict_last_policy();

    float sA = edge_partial((long long)hA, (long long)tA, rA, lane, pol);
    float sB = edge_partial((long long)hB, (long long)tB, rB, lane, pol);

    // Pair-combine: lanes 0-15 accumulate edge A, lanes 16-31 edge B.
    bool hi = (lane & 16) != 0;
    float send = hi ? sA : sB;
    float keep = hi ? sB : sA;
    float v = keep + __shfl_xor_sync(0xffffffffu, send, 16);
    #pragma unroll
    for (int off = 8; off > 0; off >>= 1)
        v += __shfl_xor_sync(0xffffffffu, v, off);

    float res = fmaf(v, g_scale, g_bias);
    if (lane == 0) out[e0] = res;
    if (lane == 16 && hasB) out[e0 + 1] = res;
}

extern "C" void kernel_launch(void* const* d_in, const int* in_sizes, int n_in,
                              void* d_out, int out_size) {
    const float* nodes       = (const float*)d_in[0];
    const int*   edge_index  = (const int*)d_in[1];
    const int*   rel_type    = (const int*)d_in[2];
    const float* rel_emb     = (const float*)d_in[3];
    const float* temperature = (const float*)d_in[4];
    const float* bias        = (const float*)d_in[5];
    float*       out         = (float*)d_out;

    int num_edges = in_sizes[2];
    long long n_elems8 = (long long)in_sizes[0] / 8;

    int conv_blocks = (int)((n_elems8 + 255) / 256);
    prep_kernel<<<ROT_BLOCKS + conv_blocks, 256>>>(rel_emb, nodes,
                                                   temperature, bias, n_elems8);

    int pairs = (num_edges + 1) / 2;                 // one warp per 2 edges
    int warps_per_block = 256 / 32;
    int blocks = (pairs + warps_per_block - 1) / warps_per_block;
    rotate_score_kernel<<<blocks, 256>>>(edge_index, rel_type, out, num_edges);
}